// round 16
// baseline (speedup 1.0000x reference)
#include <cuda_runtime.h>
#include <cuda_fp16.h>
#include <math.h>
#include <cfloat>

// ---------------------------------------------------------------------------
// VQGAN forward. dec1-3: mma.sync fp16 1-term (fp32 acc), K32/stage, packed-h2
// activations end-to-end (vq/dec1/dec2 emit h2 channel-pairs; staging = uint4
// copy). Encoder fp32 scalar with row-shared loads (exact argmin). dec4 scalar.
// ---------------------------------------------------------------------------

#define NB 2

__device__ float g_h1[(size_t)NB * 64 * 32 * 32 * 32];
__device__ float g_h2[(size_t)NB * 128 * 16 * 16 * 16];
__device__ float g_h3[(size_t)NB * 256 * 8 * 8 * 8];
__device__ float g_lat[(size_t)NB * 256 * 512];
__device__ float g_d3[(size_t)NB * 64 * 64 * 64 * 64];
// packed h2 activations: [ci_pair][spatial]
__device__ unsigned g_q2[(size_t)NB * 128 * 512];
__device__ unsigned g_d1h[(size_t)NB * 128 * 16 * 16 * 16];
__device__ unsigned g_d2h[(size_t)NB * 64 * 32 * 32 * 32];
// repacked fp16 B: [cls][cog][stage][g(2)][co(64)][12] words
__device__ unsigned g_wpk1[8 * 4 * 64 * 1536];
__device__ unsigned g_wpk2[8 * 2 * 64 * 1536];
__device__ unsigned g_wpk3[8 * 1 * 32 * 1536];

__device__ __forceinline__ unsigned pack_h2(float a, float b) {
    __half2 t = __floats2half2_rn(a, b);
    return *reinterpret_cast<unsigned*>(&t);
}
__device__ __forceinline__ void mma16816(float* c, const unsigned* a, const unsigned* b) {
    asm volatile("mma.sync.aligned.m16n8k16.row.col.f32.f16.f16.f32 "
                 "{%0,%1,%2,%3},{%4,%5,%6,%7},{%8,%9},{%0,%1,%2,%3};"
                 : "+f"(c[0]), "+f"(c[1]), "+f"(c[2]), "+f"(c[3])
                 : "r"(a[0]), "r"(a[1]), "r"(a[2]), "r"(a[3]),
                   "r"(b[0]), "r"(b[1]));
}
__device__ __forceinline__ int kparity(int r, int t) { return r ? (2 - 2 * t) : (1 + 2 * t); }

// ---------------------------------------------------------------------------
// Weight repack: w[ci][co][tap] fp32 -> [cls][cog][s][g][co][12] h2 words.
// ---------------------------------------------------------------------------
template <int Cin, int Cout>
__global__ void repackW(const float* __restrict__ w, unsigned* __restrict__ wpk)
{
    constexpr int NIT = Cin / 4, COG = Cout / 64;
    int i = blockIdx.x * 256 + threadIdx.x;
    if (i >= 8 * COG * NIT * 1536) return;
    int slot = i % 12;
    int co = (i / 12) & 63;
    int g = (i / (12 * 64)) & 1;
    int T = i / (12 * 64 * 2);
    int s = T % NIT, cog = (T / NIT) % COG, cls = T / (NIT * COG);
    unsigned v = 0;
    if (slot < 8) {
        int rz = (cls >> 2) & 1, ry = (cls >> 1) & 1, rx = cls & 1;
        int tz = (slot >> 2) & 1, ty = (slot >> 1) & 1, tx = slot & 1;
        int tap = kparity(rz, tz) * 16 + kparity(ry, ty) * 4 + kparity(rx, tx);
        int ci0 = 4 * s + 2 * g;
        size_t base = (size_t)ci0 * Cout * 64 + (size_t)(cog * 64 + co) * 64 + tap;
        v = pack_h2(w[base], w[base + (size_t)Cout * 64]);
    }
    wpk[i] = v;
}

// ---------------------------------------------------------------------------
// convT k4 s2 p1 + ReLU via tensor cores (fp16 1-term), K32/stage (4 ci).
// Input: packed h2 [Cin/2][Din^3]. Output: packed h2 (PACK_OUT) or fp32.
// ---------------------------------------------------------------------------
template <int Cin, int Cout, int Din, int ZT, int R, bool PACK_OUT>
__global__ void __launch_bounds__(256)
convT_mma(const unsigned* __restrict__ in2, const unsigned* __restrict__ wpk,
          const float* __restrict__ bias, float* __restrict__ out32,
          unsigned* __restrict__ outp)
{
    constexpr int Dout = 2 * Din;
    constexpr int XQ = Din / 4;
    constexpr int XSP = Din + 4;
    constexpr int YS = R + 2;
    constexpr int ZSP = YS * XSP;
    constexpr int PLANES = ZT + 1;
    constexpr int TILE = PLANES * ZSP;
    constexpr int NIT = Cin / 4;
    constexpr int COG = Cout / 64;
    constexpr int TPY = Din / R;
    constexpr int ITEMS = PLANES * YS * 2 * XQ;
    constexpr size_t D3 = (size_t)Din * Din * Din;

    __shared__ unsigned rawHi[2][2][TILE];
    __shared__ unsigned Bh_s[2][2 * 64 * 12];

    const int tid = threadIdx.x, lane = tid & 31, wid = tid >> 5;
    const int wm = wid & 3, wn = wid >> 2;
    const int bzz = blockIdx.z, bb = bzz >> 3, cls = bzz & 7;
    const int rz = (cls >> 2) & 1, ry = (cls >> 1) & 1, rx = cls & 1;
    const int zoff1 = rz ? 1 : -1, yoff1 = ry ? 1 : -1, xoff1 = rx ? 1 : -1;
    const int mz0 = (blockIdx.x / TPY) * ZT;
    const int my0 = (blockIdx.x % TPY) * R;
    const int coBase = blockIdx.y * 64;
    const int zlo = 1 - rz;

    // ---- A staging: one uint4 (4 x-positions of one cipair) per thread ----
    bool st_ok = false;
    int st_g = 0, st_soff = 0;
    size_t st_goff = 0;
    if (tid < ITEMS) {
        int qx = tid % XQ;
        st_g = (tid / XQ) & 1;
        int yy = (tid / (XQ * 2)) % YS;
        int p = tid / (XQ * 2 * YS);
        int gz = mz0 + p - zlo;
        int gy = my0 + yy - 1;
        st_ok = (unsigned)gz < (unsigned)Din && (unsigned)gy < (unsigned)Din;
        st_goff = (size_t)bb * (Cin / 2) * D3 + (size_t)(st_ok ? gz : 0) * Din * Din
                  + (size_t)(st_ok ? gy : 0) * Din + qx * 4;
        st_soff = p * ZSP + yy * XSP + qx * 4;
    }

    // ---- A fragment word offsets (halo x -> static zero slots) ----
    const int kp = lane & 3;
    int aoff[2][2][2];
#pragma unroll
    for (int t = 0; t < 2; t++)
#pragma unroll
        for (int h = 0; h < 2; h++)
#pragma unroll
            for (int q = 0; q < 2; q++) {
                int tap = kp + 4 * q;
                int tzk = (tap >> 2) & 1, tyk = (tap >> 1) & 1, txk = tap & 1;
                int mloc = wm * 32 + t * 16 + (lane >> 2) + h * 8;
                int mzl = mloc / (R * Din);
                int rem = mloc % (R * Din);
                int myl = rem / Din, mx = rem % Din;
                int plane = mzl + (tzk ? zoff1 : 0) + zlo;
                int yy = myl + (tyk ? yoff1 : 0) + 1;
                int xr = mx + (txk ? xoff1 : 0);
                int slot = (xr < 0) ? (Din + 1) : xr;
                aoff[t][h][q] = plane * ZSP + yy * XSP + slot;
            }

    int boff[4];
#pragma unroll
    for (int j = 0; j < 4; j++)
        boff[j] = (wn * 32 + j * 8 + (lane >> 2)) * 12 + kp;

    float C[2][4][4];
#pragma unroll
    for (int t = 0; t < 2; t++)
#pragma unroll
        for (int j = 0; j < 4; j++)
#pragma unroll
            for (int k = 0; k < 4; k++) C[t][j][k] = 0.f;

    for (int i = tid; i < 2 * 2 * TILE; i += 256)
        (&rawHi[0][0][0])[i] = 0u;

    const unsigned* bsrc = wpk + (size_t)(cls * COG + blockIdx.y) * NIT * 1536;

    uint4 rv, bv0, bv1;

#define STAGE_REGS(IT)                                                          \
    {                                                                           \
        if (st_ok)                                                              \
            rv = *(const uint4*)(in2 + st_goff + (size_t)(2 * (IT) + st_g) * D3); \
        const uint4* bs = (const uint4*)(bsrc + (size_t)(IT) * 1536);           \
        bv0 = __ldg(bs + tid);                                                  \
        if (tid < 128) bv1 = __ldg(bs + tid + 256);                             \
    }

#define STAGE_STORE(BF)                                                         \
    {                                                                           \
        if (st_ok) *(uint4*)&rawHi[BF][st_g][st_soff] = rv;                     \
        ((uint4*)&Bh_s[BF][0])[tid] = bv0;                                      \
        if (tid < 128) ((uint4*)&Bh_s[BF][0])[tid + 256] = bv1;                 \
    }

#define COMPUTE(BF)                                                             \
    {                                                                           \
        _Pragma("unroll")                                                       \
        for (int g = 0; g < 2; g++) {                                           \
            unsigned Ah[2][4];                                                  \
            _Pragma("unroll")                                                   \
            for (int t = 0; t < 2; t++) {                                       \
                Ah[t][0] = rawHi[BF][g][aoff[t][0][0]];                         \
                Ah[t][1] = rawHi[BF][g][aoff[t][1][0]];                         \
                Ah[t][2] = rawHi[BF][g][aoff[t][0][1]];                         \
                Ah[t][3] = rawHi[BF][g][aoff[t][1][1]];                         \
            }                                                                   \
            unsigned Bh[4][2];                                                  \
            _Pragma("unroll")                                                   \
            for (int j = 0; j < 4; j++) {                                       \
                Bh[j][0] = Bh_s[BF][g * 768 + boff[j]];                         \
                Bh[j][1] = Bh_s[BF][g * 768 + boff[j] + 4];                     \
            }                                                                   \
            _Pragma("unroll")                                                   \
            for (int t = 0; t < 2; t++)                                         \
                _Pragma("unroll")                                               \
                for (int j = 0; j < 4; j++)                                     \
                    mma16816(C[t][j], Ah[t], Bh[j]);                            \
        }                                                                       \
    }

    STAGE_REGS(0);
    __syncthreads();
    STAGE_STORE(0);
    __syncthreads();

    int bf = 0;
    for (int it = 0; it < NIT; ++it) {
        bool more = (it + 1 < NIT);
        if (more) STAGE_REGS(it + 1);
        COMPUTE(bf);
        if (more) {
            STAGE_STORE(bf ^ 1);
            bf ^= 1;
            __syncthreads();
        }
    }

#undef STAGE_REGS
#undef STAGE_STORE
#undef COMPUTE

    // ---- epilogue: bias + ReLU + store (packed h2 or fp32) ----
#pragma unroll
    for (int j = 0; j < 4; j++) {
        int n0 = coBase + wn * 32 + j * 8 + (lane & 3) * 2;
        float bv_0 = bias[n0], bv_1 = bias[n0 + 1];
#pragma unroll
        for (int t = 0; t < 2; t++)
#pragma unroll
            for (int h = 0; h < 2; h++) {
                int mloc = wm * 32 + t * 16 + (lane >> 2) + h * 8;
                int mzl = mloc / (R * Din);
                int rem = mloc % (R * Din);
                int myl = rem / Din, mx = rem % Din;
                int oz = 2 * (mz0 + mzl) + rz;
                int oy = 2 * (my0 + myl) + ry;
                int ox = 2 * mx + rx;
                float v0 = fmaxf(C[t][j][2 * h] + bv_0, 0.f);
                float v1 = fmaxf(C[t][j][2 * h + 1] + bv_1, 0.f);
                size_t sp = (size_t)oz * Dout * Dout + (size_t)oy * Dout + ox;
                if (PACK_OUT) {
                    outp[((size_t)bb * (Cout / 2) + (n0 >> 1)) * ((size_t)Dout * Dout * Dout) + sp] =
                        pack_h2(v0, v1);
                } else {
                    size_t a = ((size_t)bb * Cout + n0) * ((size_t)Dout * Dout * Dout) + sp;
                    out32[a] = v0;
                    out32[a + (size_t)Dout * Dout * Dout] = v1;
                }
            }
    }
}

// ---------------------------------------------------------------------------
// conv3d k=4 s=2 p=1 + ReLU, scalar fp32, row-shared loads (union of 2P+2).
// ---------------------------------------------------------------------------
template <int Cin, int Cout, int Dout, int TC, int P>
__global__ void conv_s2_relu(const float* __restrict__ in,
                             const float* __restrict__ w,
                             const float* __restrict__ bias,
                             float* __restrict__ out)
{
    constexpr int Din = 2 * Dout;
    constexpr int CI_CHUNK = (Cin < 16) ? Cin : 16;
    constexpr int NV = 2 * P + 2;
    __shared__ float ws[CI_CHUNK][TC][64];

    const int tid = threadIdx.x;
    const int coBase = blockIdx.y * TC;
    const int b = blockIdx.z;
    const int s0 = blockIdx.x * (128 * P) + tid * P;
    const int ox0 = s0 % Dout;
    const int oy = (s0 / Dout) % Dout;
    const int oz = s0 / (Dout * Dout);
    const int ixb = 2 * ox0 - 1;
    const bool xin = (ixb >= 0) && (ixb + NV - 1 <= Din - 1);

    float acc[P][TC];
#pragma unroll
    for (int p = 0; p < P; p++)
#pragma unroll
        for (int c = 0; c < TC; c++) acc[p][c] = 0.f;

    const float* inB = in + (size_t)b * Cin * Din * Din * Din;

    for (int ci0 = 0; ci0 < Cin; ci0 += CI_CHUNK) {
        for (int i = tid; i < CI_CHUNK * TC * 64; i += 128) {
            int ci = i / (TC * 64);
            int rem = i % (TC * 64);
            ws[ci][rem / 64][rem % 64] =
                w[((size_t)(coBase + rem / 64) * Cin + (ci0 + ci)) * 64 + rem % 64];
        }
        __syncthreads();

#pragma unroll 1
        for (int ci = 0; ci < CI_CHUNK; ci++) {
            const float* inC = inB + (size_t)(ci0 + ci) * Din * Din * Din;
#pragma unroll
            for (int kd = 0; kd < 4; kd++) {
                const int iz = 2 * oz + kd - 1;
                if ((unsigned)iz >= (unsigned)Din) continue;
#pragma unroll
                for (int kh = 0; kh < 4; kh++) {
                    const int iy = 2 * oy + kh - 1;
                    if ((unsigned)iy >= (unsigned)Din) continue;
                    const float* row = inC + (size_t)iz * Din * Din + (size_t)iy * Din + ixb;

                    float vals[NV];
                    if (xin) {
#pragma unroll
                        for (int j = 0; j < NV; j++) vals[j] = row[j];
                    } else {
#pragma unroll
                        for (int j = 0; j < NV; j++) {
                            int ix = ixb + j;
                            vals[j] = ((unsigned)ix < (unsigned)Din) ? row[j] : 0.f;
                        }
                    }
#pragma unroll
                    for (int kw = 0; kw < 4; kw++) {
                        const int tap = kd * 16 + kh * 4 + kw;
#pragma unroll
                        for (int c = 0; c < TC; c++) {
                            const float wv = ws[ci][c][tap];
#pragma unroll
                            for (int p = 0; p < P; p++)
                                acc[p][c] = fmaf(vals[kw + 2 * p], wv, acc[p][c]);
                        }
                    }
                }
            }
        }
        __syncthreads();
    }

#pragma unroll
    for (int c = 0; c < TC; c++) {
        float bv = bias[coBase + c];
        size_t base = (((size_t)b * Cout + coBase + c) * Dout + oz) * Dout * Dout
                      + (size_t)oy * Dout + ox0;
#pragma unroll
        for (int p = 0; p < P; p++) out[base + p] = fmaxf(acc[p][c] + bv, 0.f);
    }
}

__global__ void conv1x1(const float* __restrict__ in, const float* __restrict__ w,
                        const float* __restrict__ bias, float* __restrict__ out)
{
    __shared__ float ws[8][256];
    const int tid = threadIdx.x;
    const int coBase = blockIdx.y * 8;
    const int b = blockIdx.z;
    const int s = blockIdx.x * 128 + tid;

    for (int i = tid; i < 8 * 256; i += 128)
        ws[i / 256][i % 256] = w[(size_t)(coBase + i / 256) * 256 + (i % 256)];
    __syncthreads();

    float acc[8];
#pragma unroll
    for (int c = 0; c < 8; c++) acc[c] = 0.f;

    const float* inB = in + (size_t)b * 256 * 512 + s;
    for (int ci = 0; ci < 256; ci++) {
        float v = inB[(size_t)ci * 512];
#pragma unroll
        for (int c = 0; c < 8; c++) acc[c] += v * ws[c][ci];
    }
#pragma unroll
    for (int c = 0; c < 8; c++)
        out[((size_t)b * 256 + coBase + c) * 512 + s] = acc[c] + bias[coBase + c];
}

// ---------------------------------------------------------------------------
// VQ: writes idx (output tail) and PACKED h2 q [128 cipairs][512].
// ---------------------------------------------------------------------------
__global__ void vq_kernel(const float* __restrict__ lat, const float* __restrict__ cb,
                          unsigned* __restrict__ q2, float* __restrict__ idx_out)
{
    __shared__ float4 latS[8][64];
    __shared__ float ln[8];
    __shared__ float bd[8][128];
    __shared__ int bk[8][128];
    __shared__ int wink[8];

    const int tid = threadIdx.x;
    const int vb = blockIdx.x * 8;

    for (int i = tid; i < 8 * 64; i += 128) {
        int v = i >> 6, d4 = i & 63;
        latS[v][d4] = ((const float4*)lat)[(size_t)(vb + v) * 64 + d4];
    }
    __syncthreads();

    if (tid < 8) {
        float s = 0.f;
        for (int d4 = 0; d4 < 64; d4++) {
            float4 l = latS[tid][d4];
            s += l.x * l.x + l.y * l.y + l.z * l.z + l.w * l.w;
        }
        ln[tid] = s;
    }
    __syncthreads();

    float best[8];
    int bestk[8];
#pragma unroll
    for (int v = 0; v < 8; v++) { best[v] = FLT_MAX; bestk[v] = 0; }

    for (int j = 0; j < 8; j++) {
        const int k = tid + j * 128;
        const float4* cbr = (const float4*)(cb + (size_t)k * 256);
        float dot[8];
        float cn = 0.f;
#pragma unroll
        for (int v = 0; v < 8; v++) dot[v] = 0.f;
        for (int d4 = 0; d4 < 64; d4++) {
            float4 c = cbr[d4];
            cn += c.x * c.x + c.y * c.y + c.z * c.z + c.w * c.w;
#pragma unroll
            for (int v = 0; v < 8; v++) {
                float4 l = latS[v][d4];
                dot[v] += c.x * l.x + c.y * l.y + c.z * l.z + c.w * l.w;
            }
        }
#pragma unroll
        for (int v = 0; v < 8; v++) {
            float d2 = ln[v] - 2.f * dot[v] + cn;
            if (d2 < best[v]) { best[v] = d2; bestk[v] = k; }
        }
    }

#pragma unroll
    for (int v = 0; v < 8; v++) { bd[v][tid] = best[v]; bk[v][tid] = bestk[v]; }
    __syncthreads();
    for (int s = 64; s > 0; s >>= 1) {
        if (tid < s) {
#pragma unroll
            for (int v = 0; v < 8; v++) {
                float dB = bd[v][tid + s];
                int kB = bk[v][tid + s];
                if (dB < bd[v][tid] || (dB == bd[v][tid] && kB < bk[v][tid])) {
                    bd[v][tid] = dB; bk[v][tid] = kB;
                }
            }
        }
        __syncthreads();
    }
    if (tid < 8) {
        wink[tid] = bk[tid][0];
        if (idx_out) idx_out[vb + tid] = (float)bk[tid][0];
    }
    __syncthreads();

    // q2[b, cp, n] = pack(cb[win][2cp], cb[win][2cp+1])
    for (int i = tid; i < 8 * 128; i += 128) {
        int v = i >> 7, cp = i & 127;
        int gn = vb + v;
        int b = gn >> 9, n = gn & 511;
        const float* cr = cb + (size_t)wink[v] * 256 + 2 * cp;
        q2[((size_t)b * 128 + cp) * 512 + n] = pack_h2(cr[0], cr[1]);
    }
}

__global__ void __launch_bounds__(128)
conv_final_tanh(const float* __restrict__ in, const float* __restrict__ w,
                const float* __restrict__ bias, float* __restrict__ out)
{
    __shared__ float ws[3 * 64 * 64];
    const int tid = threadIdx.x;
    for (int i = tid; i < 3 * 64 * 64; i += 128) ws[i] = w[i];
    __syncthreads();

    const int b = blockIdx.z;
    const int z = blockIdx.y;
    const int ry = tid / 8;
    const int y = blockIdx.x * 16 + ry;
    const int x0 = (tid % 8) * 8;
    if (y >= 61) return;

    float acc[3][8];
#pragma unroll
    for (int c = 0; c < 3; c++)
#pragma unroll
        for (int p = 0; p < 8; p++) acc[c][p] = 0.f;

    const float* inB = in + (size_t)b * 64 * 64 * 64 * 64;
#pragma unroll 1
    for (int ci = 0; ci < 64; ci++) {
        const float* inC = inB + (size_t)ci * 262144;
#pragma unroll
        for (int kd = 0; kd < 4; kd++) {
            const float* pz = inC + (size_t)(z + kd) * 4096;
#pragma unroll
            for (int kh = 0; kh < 4; kh++) {
                const float* row = pz + (size_t)(y + kh) * 64;
                float v[11];
#pragma unroll
                for (int j = 0; j < 11; j++) {
                    int ix = x0 + j;
                    v[j] = (ix < 64) ? row[ix] : 0.f;
                }
#pragma unroll
                for (int kw = 0; kw < 4; kw++)
#pragma unroll
                    for (int c = 0; c < 3; c++) {
                        float wv = ws[((size_t)c * 64 + ci) * 64 + kd * 16 + kh * 4 + kw];
#pragma unroll
                        for (int p = 0; p < 8; p++) acc[c][p] = fmaf(v[kw + p], wv, acc[c][p]);
                    }
            }
        }
    }

#pragma unroll
    for (int c = 0; c < 3; c++) {
        float bv = bias[c];
        size_t base = (((size_t)b * 3 + c) * 61 + z) * 61 * 61 + (size_t)y * 61;
#pragma unroll
        for (int p = 0; p < 8; p++) {
            int x = x0 + p;
            if (x < 61) out[base + x] = tanhf(acc[c][p] + bv);
        }
    }
}

// ---------------------------------------------------------------------------

extern "C" void kernel_launch(void* const* d_in, const int* in_sizes, int n_in,
                              void* d_out, int out_size)
{
    const float* x   = (const float*)d_in[0];
    const float* ew1 = (const float*)d_in[1];  const float* eb1 = (const float*)d_in[2];
    const float* ew2 = (const float*)d_in[3];  const float* eb2 = (const float*)d_in[4];
    const float* ew3 = (const float*)d_in[5];  const float* eb3 = (const float*)d_in[6];
    const float* ew4 = (const float*)d_in[7];  const float* eb4 = (const float*)d_in[8];
    const float* cb  = (const float*)d_in[9];
    const float* dw1 = (const float*)d_in[10]; const float* db1 = (const float*)d_in[11];
    const float* dw2 = (const float*)d_in[12]; const float* db2 = (const float*)d_in[13];
    const float* dw3 = (const float*)d_in[14]; const float* db3 = (const float*)d_in[15];
    const float* dw4 = (const float*)d_in[16]; const float* db4 = (const float*)d_in[17];

    float* out = (float*)d_out;
    const int RECON = 2 * 3 * 61 * 61 * 61;
    float* idx_out = (out_size >= RECON + 1024) ? (out + RECON) : nullptr;

    float *h1, *h2, *h3, *lat, *d3;
    unsigned *q2, *d1h, *d2h, *wpk1, *wpk2, *wpk3;
    cudaGetSymbolAddress((void**)&h1, g_h1);
    cudaGetSymbolAddress((void**)&h2, g_h2);
    cudaGetSymbolAddress((void**)&h3, g_h3);
    cudaGetSymbolAddress((void**)&lat, g_lat);
    cudaGetSymbolAddress((void**)&d3, g_d3);
    cudaGetSymbolAddress((void**)&q2, g_q2);
    cudaGetSymbolAddress((void**)&d1h, g_d1h);
    cudaGetSymbolAddress((void**)&d2h, g_d2h);
    cudaGetSymbolAddress((void**)&wpk1, g_wpk1);
    cudaGetSymbolAddress((void**)&wpk2, g_wpk2);
    cudaGetSymbolAddress((void**)&wpk3, g_wpk3);

    // weight repacks
    repackW<256, 256><<<(8 * 4 * 64 * 1536 + 255) / 256, 256>>>(dw1, wpk1);
    repackW<256, 128><<<(8 * 2 * 64 * 1536 + 255) / 256, 256>>>(dw2, wpk2);
    repackW<128, 64><<<(8 * 1 * 32 * 1536 + 255) / 256, 256>>>(dw3, wpk3);

    // encoder (scalar fp32, row-shared loads; exact argmin)
    conv_s2_relu<3, 64, 32, 8, 4><<<dim3(64, 8, 2), 128>>>(x, ew1, eb1, h1);
    conv_s2_relu<64, 128, 16, 8, 4><<<dim3(8, 16, 2), 128>>>(h1, ew2, eb2, h2);
    conv_s2_relu<128, 256, 8, 2, 2><<<dim3(2, 128, 2), 128>>>(h2, ew3, eb3, h3);
    conv1x1<<<dim3(4, 32, 2), 128>>>(h3, ew4, eb4, lat);

    // vector quantization (writes packed q + idx)
    vq_kernel<<<128, 128>>>(lat, cb, q2, idx_out);

    // decoder: packed-h2 activation chain
    convT_mma<256, 256, 8, 2, 8, true><<<dim3(4, 4, 16), 256>>>(q2, wpk1, db1, nullptr, d1h);
    convT_mma<256, 128, 16, 1, 8, true><<<dim3(32, 2, 16), 256>>>(d1h, wpk2, db2, nullptr, d2h);
    convT_mma<128, 64, 32, 1, 4, false><<<dim3(256, 1, 16), 256>>>(d2h, wpk3, db3, d3, nullptr);
    conv_final_tanh<<<dim3(4, 61, 2), 128>>>(d3, dw4, db4, out);
}

// round 17
// speedup vs baseline: 1.1703x; 1.1703x over previous
#include <cuda_runtime.h>
#include <cuda_fp16.h>
#include <math.h>
#include <cfloat>

// ---------------------------------------------------------------------------
// VQGAN forward. dec1-3: mma.sync fp16 1-term (fp32 acc), K32/stage, packed-h2
// activations end-to-end (vq/dec1/dec2 emit h2 channel-pairs; staging = uint4
// copy). Encoder fp32 scalar per-tap loads (R15 exact; argmin-exact). dec4 scalar.
// ---------------------------------------------------------------------------

#define NB 2

__device__ float g_h1[(size_t)NB * 64 * 32 * 32 * 32];
__device__ float g_h2[(size_t)NB * 128 * 16 * 16 * 16];
__device__ float g_h3[(size_t)NB * 256 * 8 * 8 * 8];
__device__ float g_lat[(size_t)NB * 256 * 512];
__device__ float g_d3[(size_t)NB * 64 * 64 * 64 * 64];
// packed h2 activations: [ci_pair][spatial]
__device__ unsigned g_q2[(size_t)NB * 128 * 512];
__device__ unsigned g_d1h[(size_t)NB * 128 * 16 * 16 * 16];
__device__ unsigned g_d2h[(size_t)NB * 64 * 32 * 32 * 32];
// repacked fp16 B: [cls][cog][stage][g(2)][co(64)][12] words
__device__ unsigned g_wpk1[8 * 4 * 64 * 1536];
__device__ unsigned g_wpk2[8 * 2 * 64 * 1536];
__device__ unsigned g_wpk3[8 * 1 * 32 * 1536];

__device__ __forceinline__ unsigned pack_h2(float a, float b) {
    __half2 t = __floats2half2_rn(a, b);
    return *reinterpret_cast<unsigned*>(&t);
}
__device__ __forceinline__ void mma16816(float* c, const unsigned* a, const unsigned* b) {
    asm volatile("mma.sync.aligned.m16n8k16.row.col.f32.f16.f16.f32 "
                 "{%0,%1,%2,%3},{%4,%5,%6,%7},{%8,%9},{%0,%1,%2,%3};"
                 : "+f"(c[0]), "+f"(c[1]), "+f"(c[2]), "+f"(c[3])
                 : "r"(a[0]), "r"(a[1]), "r"(a[2]), "r"(a[3]),
                   "r"(b[0]), "r"(b[1]));
}
__device__ __forceinline__ int kparity(int r, int t) { return r ? (2 - 2 * t) : (1 + 2 * t); }

// ---------------------------------------------------------------------------
// Weight repack: w[ci][co][tap] fp32 -> [cls][cog][s][g][co][12] h2 words.
// ---------------------------------------------------------------------------
template <int Cin, int Cout>
__global__ void repackW(const float* __restrict__ w, unsigned* __restrict__ wpk)
{
    constexpr int NIT = Cin / 4, COG = Cout / 64;
    int i = blockIdx.x * 256 + threadIdx.x;
    if (i >= 8 * COG * NIT * 1536) return;
    int slot = i % 12;
    int co = (i / 12) & 63;
    int g = (i / (12 * 64)) & 1;
    int T = i / (12 * 64 * 2);
    int s = T % NIT, cog = (T / NIT) % COG, cls = T / (NIT * COG);
    unsigned v = 0;
    if (slot < 8) {
        int rz = (cls >> 2) & 1, ry = (cls >> 1) & 1, rx = cls & 1;
        int tz = (slot >> 2) & 1, ty = (slot >> 1) & 1, tx = slot & 1;
        int tap = kparity(rz, tz) * 16 + kparity(ry, ty) * 4 + kparity(rx, tx);
        int ci0 = 4 * s + 2 * g;
        size_t base = (size_t)ci0 * Cout * 64 + (size_t)(cog * 64 + co) * 64 + tap;
        v = pack_h2(w[base], w[base + (size_t)Cout * 64]);
    }
    wpk[i] = v;
}

// ---------------------------------------------------------------------------
// convT k4 s2 p1 + ReLU via tensor cores (fp16 1-term), K32/stage (4 ci).
// Input: packed h2 [Cin/2][Din^3]. Output: packed h2 (PACK_OUT) or fp32.
// ---------------------------------------------------------------------------
template <int Cin, int Cout, int Din, int ZT, int R, bool PACK_OUT>
__global__ void __launch_bounds__(256)
convT_mma(const unsigned* __restrict__ in2, const unsigned* __restrict__ wpk,
          const float* __restrict__ bias, float* __restrict__ out32,
          unsigned* __restrict__ outp)
{
    constexpr int Dout = 2 * Din;
    constexpr int XQ = Din / 4;
    constexpr int XSP = Din + 4;
    constexpr int YS = R + 2;
    constexpr int ZSP = YS * XSP;
    constexpr int PLANES = ZT + 1;
    constexpr int TILE = PLANES * ZSP;
    constexpr int NIT = Cin / 4;
    constexpr int COG = Cout / 64;
    constexpr int TPY = Din / R;
    constexpr int ITEMS = PLANES * YS * 2 * XQ;
    constexpr size_t D3 = (size_t)Din * Din * Din;

    __shared__ unsigned rawHi[2][2][TILE];
    __shared__ unsigned Bh_s[2][2 * 64 * 12];

    const int tid = threadIdx.x, lane = tid & 31, wid = tid >> 5;
    const int wm = wid & 3, wn = wid >> 2;
    const int bzz = blockIdx.z, bb = bzz >> 3, cls = bzz & 7;
    const int rz = (cls >> 2) & 1, ry = (cls >> 1) & 1, rx = cls & 1;
    const int zoff1 = rz ? 1 : -1, yoff1 = ry ? 1 : -1, xoff1 = rx ? 1 : -1;
    const int mz0 = (blockIdx.x / TPY) * ZT;
    const int my0 = (blockIdx.x % TPY) * R;
    const int coBase = blockIdx.y * 64;
    const int zlo = 1 - rz;

    // ---- A staging: one uint4 (4 x-positions of one cipair) per thread ----
    bool st_ok = false;
    int st_g = 0, st_soff = 0;
    size_t st_goff = 0;
    if (tid < ITEMS) {
        int qx = tid % XQ;
        st_g = (tid / XQ) & 1;
        int yy = (tid / (XQ * 2)) % YS;
        int p = tid / (XQ * 2 * YS);
        int gz = mz0 + p - zlo;
        int gy = my0 + yy - 1;
        st_ok = (unsigned)gz < (unsigned)Din && (unsigned)gy < (unsigned)Din;
        st_goff = (size_t)bb * (Cin / 2) * D3 + (size_t)(st_ok ? gz : 0) * Din * Din
                  + (size_t)(st_ok ? gy : 0) * Din + qx * 4;
        st_soff = p * ZSP + yy * XSP + qx * 4;
    }

    // ---- A fragment word offsets (halo x -> static zero slots) ----
    const int kp = lane & 3;
    int aoff[2][2][2];
#pragma unroll
    for (int t = 0; t < 2; t++)
#pragma unroll
        for (int h = 0; h < 2; h++)
#pragma unroll
            for (int q = 0; q < 2; q++) {
                int tap = kp + 4 * q;
                int tzk = (tap >> 2) & 1, tyk = (tap >> 1) & 1, txk = tap & 1;
                int mloc = wm * 32 + t * 16 + (lane >> 2) + h * 8;
                int mzl = mloc / (R * Din);
                int rem = mloc % (R * Din);
                int myl = rem / Din, mx = rem % Din;
                int plane = mzl + (tzk ? zoff1 : 0) + zlo;
                int yy = myl + (tyk ? yoff1 : 0) + 1;
                int xr = mx + (txk ? xoff1 : 0);
                int slot = (xr < 0) ? (Din + 1) : xr;
                aoff[t][h][q] = plane * ZSP + yy * XSP + slot;
            }

    int boff[4];
#pragma unroll
    for (int j = 0; j < 4; j++)
        boff[j] = (wn * 32 + j * 8 + (lane >> 2)) * 12 + kp;

    float C[2][4][4];
#pragma unroll
    for (int t = 0; t < 2; t++)
#pragma unroll
        for (int j = 0; j < 4; j++)
#pragma unroll
            for (int k = 0; k < 4; k++) C[t][j][k] = 0.f;

    for (int i = tid; i < 2 * 2 * TILE; i += 256)
        (&rawHi[0][0][0])[i] = 0u;

    const unsigned* bsrc = wpk + (size_t)(cls * COG + blockIdx.y) * NIT * 1536;

    uint4 rv, bv0, bv1;

#define STAGE_REGS(IT)                                                          \
    {                                                                           \
        if (st_ok)                                                              \
            rv = *(const uint4*)(in2 + st_goff + (size_t)(2 * (IT) + st_g) * D3); \
        const uint4* bs = (const uint4*)(bsrc + (size_t)(IT) * 1536);           \
        bv0 = __ldg(bs + tid);                                                  \
        if (tid < 128) bv1 = __ldg(bs + tid + 256);                             \
    }

#define STAGE_STORE(BF)                                                         \
    {                                                                           \
        if (st_ok) *(uint4*)&rawHi[BF][st_g][st_soff] = rv;                     \
        ((uint4*)&Bh_s[BF][0])[tid] = bv0;                                      \
        if (tid < 128) ((uint4*)&Bh_s[BF][0])[tid + 256] = bv1;                 \
    }

#define COMPUTE(BF)                                                             \
    {                                                                           \
        _Pragma("unroll")                                                       \
        for (int g = 0; g < 2; g++) {                                           \
            unsigned Ah[2][4];                                                  \
            _Pragma("unroll")                                                   \
            for (int t = 0; t < 2; t++) {                                       \
                Ah[t][0] = rawHi[BF][g][aoff[t][0][0]];                         \
                Ah[t][1] = rawHi[BF][g][aoff[t][1][0]];                         \
                Ah[t][2] = rawHi[BF][g][aoff[t][0][1]];                         \
                Ah[t][3] = rawHi[BF][g][aoff[t][1][1]];                         \
            }                                                                   \
            unsigned Bh[4][2];                                                  \
            _Pragma("unroll")                                                   \
            for (int j = 0; j < 4; j++) {                                       \
                Bh[j][0] = Bh_s[BF][g * 768 + boff[j]];                         \
                Bh[j][1] = Bh_s[BF][g * 768 + boff[j] + 4];                     \
            }                                                                   \
            _Pragma("unroll")                                                   \
            for (int t = 0; t < 2; t++)                                         \
                _Pragma("unroll")                                               \
                for (int j = 0; j < 4; j++)                                     \
                    mma16816(C[t][j], Ah[t], Bh[j]);                            \
        }                                                                       \
    }

    STAGE_REGS(0);
    __syncthreads();
    STAGE_STORE(0);
    __syncthreads();

    int bf = 0;
    for (int it = 0; it < NIT; ++it) {
        bool more = (it + 1 < NIT);
        if (more) STAGE_REGS(it + 1);
        COMPUTE(bf);
        if (more) {
            STAGE_STORE(bf ^ 1);
            bf ^= 1;
            __syncthreads();
        }
    }

#undef STAGE_REGS
#undef STAGE_STORE
#undef COMPUTE

    // ---- epilogue: bias + ReLU + store (packed h2 or fp32) ----
#pragma unroll
    for (int j = 0; j < 4; j++) {
        int n0 = coBase + wn * 32 + j * 8 + (lane & 3) * 2;
        float bv_0 = bias[n0], bv_1 = bias[n0 + 1];
#pragma unroll
        for (int t = 0; t < 2; t++)
#pragma unroll
            for (int h = 0; h < 2; h++) {
                int mloc = wm * 32 + t * 16 + (lane >> 2) + h * 8;
                int mzl = mloc / (R * Din);
                int rem = mloc % (R * Din);
                int myl = rem / Din, mx = rem % Din;
                int oz = 2 * (mz0 + mzl) + rz;
                int oy = 2 * (my0 + myl) + ry;
                int ox = 2 * mx + rx;
                float v0 = fmaxf(C[t][j][2 * h] + bv_0, 0.f);
                float v1 = fmaxf(C[t][j][2 * h + 1] + bv_1, 0.f);
                size_t sp = (size_t)oz * Dout * Dout + (size_t)oy * Dout + ox;
                if (PACK_OUT) {
                    outp[((size_t)bb * (Cout / 2) + (n0 >> 1)) * ((size_t)Dout * Dout * Dout) + sp] =
                        pack_h2(v0, v1);
                } else {
                    size_t a = ((size_t)bb * Cout + n0) * ((size_t)Dout * Dout * Dout) + sp;
                    out32[a] = v0;
                    out32[a + (size_t)Dout * Dout * Dout] = v1;
                }
            }
    }
}

// ---------------------------------------------------------------------------
// conv3d k=4 s=2 p=1 + ReLU, scalar fp32 per-tap loads (R15 exact).
// ---------------------------------------------------------------------------
template <int Cin, int Cout, int Dout, int TC, int P>
__global__ void conv_s2_relu(const float* __restrict__ in,
                             const float* __restrict__ w,
                             const float* __restrict__ bias,
                             float* __restrict__ out)
{
    constexpr int Din = 2 * Dout;
    constexpr int CI_CHUNK = (Cin < 16) ? Cin : 16;
    __shared__ float ws[CI_CHUNK][TC][64];

    const int tid = threadIdx.x;
    const int coBase = blockIdx.y * TC;
    const int b = blockIdx.z;
    const int s0 = blockIdx.x * (128 * P) + tid * P;
    const int ox0 = s0 % Dout;
    const int oy = (s0 / Dout) % Dout;
    const int oz = s0 / (Dout * Dout);

    float acc[P][TC];
#pragma unroll
    for (int p = 0; p < P; p++)
#pragma unroll
        for (int c = 0; c < TC; c++) acc[p][c] = 0.f;

    const float* inB = in + (size_t)b * Cin * Din * Din * Din;

    for (int ci0 = 0; ci0 < Cin; ci0 += CI_CHUNK) {
        const int nload = CI_CHUNK * TC * 64;
        for (int i = tid; i < nload; i += 128) {
            int ci = i / (TC * 64);
            int rem = i % (TC * 64);
            int co = rem / 64;
            int tap = rem % 64;
            ws[ci][co][tap] = w[((size_t)(coBase + co) * Cin + (ci0 + ci)) * 64 + tap];
        }
        __syncthreads();

#pragma unroll 1
        for (int ci = 0; ci < CI_CHUNK; ci++) {
            const float* inC = inB + (size_t)(ci0 + ci) * Din * Din * Din;
#pragma unroll
            for (int kd = 0; kd < 4; kd++) {
                const int iz = 2 * oz + kd - 1;
                if ((unsigned)iz >= (unsigned)Din) continue;
#pragma unroll
                for (int kh = 0; kh < 4; kh++) {
                    const int iy = 2 * oy + kh - 1;
                    if ((unsigned)iy >= (unsigned)Din) continue;
                    const float* row = inC + (size_t)iz * Din * Din + (size_t)iy * Din;
#pragma unroll
                    for (int kw = 0; kw < 4; kw++) {
                        const int ixb = 2 * ox0 + kw - 1;
                        float v[P];
#pragma unroll
                        for (int p = 0; p < P; p++) {
                            int ix = ixb + 2 * p;
                            v[p] = ((unsigned)ix < (unsigned)Din) ? row[ix] : 0.f;
                        }
                        const int tap = kd * 16 + kh * 4 + kw;
#pragma unroll
                        for (int c = 0; c < TC; c++) {
                            float wv = ws[ci][c][tap];
#pragma unroll
                            for (int p = 0; p < P; p++) acc[p][c] += v[p] * wv;
                        }
                    }
                }
            }
        }
        __syncthreads();
    }

#pragma unroll
    for (int c = 0; c < TC; c++) {
        float bv = bias[coBase + c];
        size_t base = (((size_t)b * Cout + coBase + c) * Dout + oz) * Dout * Dout
                      + (size_t)oy * Dout + ox0;
#pragma unroll
        for (int p = 0; p < P; p++) out[base + p] = fmaxf(acc[p][c] + bv, 0.f);
    }
}

__global__ void conv1x1(const float* __restrict__ in, const float* __restrict__ w,
                        const float* __restrict__ bias, float* __restrict__ out)
{
    __shared__ float ws[8][256];
    const int tid = threadIdx.x;
    const int coBase = blockIdx.y * 8;
    const int b = blockIdx.z;
    const int s = blockIdx.x * 128 + tid;

    for (int i = tid; i < 8 * 256; i += 128)
        ws[i / 256][i % 256] = w[(size_t)(coBase + i / 256) * 256 + (i % 256)];
    __syncthreads();

    float acc[8];
#pragma unroll
    for (int c = 0; c < 8; c++) acc[c] = 0.f;

    const float* inB = in + (size_t)b * 256 * 512 + s;
    for (int ci = 0; ci < 256; ci++) {
        float v = inB[(size_t)ci * 512];
#pragma unroll
        for (int c = 0; c < 8; c++) acc[c] += v * ws[c][ci];
    }
#pragma unroll
    for (int c = 0; c < 8; c++)
        out[((size_t)b * 256 + coBase + c) * 512 + s] = acc[c] + bias[coBase + c];
}

// ---------------------------------------------------------------------------
// VQ: writes idx (output tail) and PACKED h2 q [128 cipairs][512].
// ---------------------------------------------------------------------------
__global__ void vq_kernel(const float* __restrict__ lat, const float* __restrict__ cb,
                          unsigned* __restrict__ q2, float* __restrict__ idx_out)
{
    __shared__ float4 latS[8][64];
    __shared__ float ln[8];
    __shared__ float bd[8][128];
    __shared__ int bk[8][128];
    __shared__ int wink[8];

    const int tid = threadIdx.x;
    const int vb = blockIdx.x * 8;

    for (int i = tid; i < 8 * 64; i += 128) {
        int v = i >> 6, d4 = i & 63;
        latS[v][d4] = ((const float4*)lat)[(size_t)(vb + v) * 64 + d4];
    }
    __syncthreads();

    if (tid < 8) {
        float s = 0.f;
        for (int d4 = 0; d4 < 64; d4++) {
            float4 l = latS[tid][d4];
            s += l.x * l.x + l.y * l.y + l.z * l.z + l.w * l.w;
        }
        ln[tid] = s;
    }
    __syncthreads();

    float best[8];
    int bestk[8];
#pragma unroll
    for (int v = 0; v < 8; v++) { best[v] = FLT_MAX; bestk[v] = 0; }

    for (int j = 0; j < 8; j++) {
        const int k = tid + j * 128;
        const float4* cbr = (const float4*)(cb + (size_t)k * 256);
        float dot[8];
        float cn = 0.f;
#pragma unroll
        for (int v = 0; v < 8; v++) dot[v] = 0.f;
        for (int d4 = 0; d4 < 64; d4++) {
            float4 c = cbr[d4];
            cn += c.x * c.x + c.y * c.y + c.z * c.z + c.w * c.w;
#pragma unroll
            for (int v = 0; v < 8; v++) {
                float4 l = latS[v][d4];
                dot[v] += c.x * l.x + c.y * l.y + c.z * l.z + c.w * l.w;
            }
        }
#pragma unroll
        for (int v = 0; v < 8; v++) {
            float d2 = ln[v] - 2.f * dot[v] + cn;
            if (d2 < best[v]) { best[v] = d2; bestk[v] = k; }
        }
    }

#pragma unroll
    for (int v = 0; v < 8; v++) { bd[v][tid] = best[v]; bk[v][tid] = bestk[v]; }
    __syncthreads();
    for (int s = 64; s > 0; s >>= 1) {
        if (tid < s) {
#pragma unroll
            for (int v = 0; v < 8; v++) {
                float dB = bd[v][tid + s];
                int kB = bk[v][tid + s];
                if (dB < bd[v][tid] || (dB == bd[v][tid] && kB < bk[v][tid])) {
                    bd[v][tid] = dB; bk[v][tid] = kB;
                }
            }
        }
        __syncthreads();
    }
    if (tid < 8) {
        wink[tid] = bk[tid][0];
        if (idx_out) idx_out[vb + tid] = (float)bk[tid][0];
    }
    __syncthreads();

    for (int i = tid; i < 8 * 128; i += 128) {
        int v = i >> 7, cp = i & 127;
        int gn = vb + v;
        int b = gn >> 9, n = gn & 511;
        const float* cr = cb + (size_t)wink[v] * 256 + 2 * cp;
        q2[((size_t)b * 128 + cp) * 512 + n] = pack_h2(cr[0], cr[1]);
    }
}

__global__ void __launch_bounds__(128)
conv_final_tanh(const float* __restrict__ in, const float* __restrict__ w,
                const float* __restrict__ bias, float* __restrict__ out)
{
    __shared__ float ws[3 * 64 * 64];
    const int tid = threadIdx.x;
    for (int i = tid; i < 3 * 64 * 64; i += 128) ws[i] = w[i];
    __syncthreads();

    const int b = blockIdx.z;
    const int z = blockIdx.y;
    const int ry = tid / 8;
    const int y = blockIdx.x * 16 + ry;
    const int x0 = (tid % 8) * 8;
    if (y >= 61) return;

    float acc[3][8];
#pragma unroll
    for (int c = 0; c < 3; c++)
#pragma unroll
        for (int p = 0; p < 8; p++) acc[c][p] = 0.f;

    const float* inB = in + (size_t)b * 64 * 64 * 64 * 64;
#pragma unroll 1
    for (int ci = 0; ci < 64; ci++) {
        const float* inC = inB + (size_t)ci * 262144;
#pragma unroll
        for (int kd = 0; kd < 4; kd++) {
            const float* pz = inC + (size_t)(z + kd) * 4096;
#pragma unroll
            for (int kh = 0; kh < 4; kh++) {
                const float* row = pz + (size_t)(y + kh) * 64;
                float v[11];
#pragma unroll
                for (int j = 0; j < 11; j++) {
                    int ix = x0 + j;
                    v[j] = (ix < 64) ? row[ix] : 0.f;
                }
#pragma unroll
                for (int kw = 0; kw < 4; kw++)
#pragma unroll
                    for (int c = 0; c < 3; c++) {
                        float wv = ws[((size_t)c * 64 + ci) * 64 + kd * 16 + kh * 4 + kw];
#pragma unroll
                        for (int p = 0; p < 8; p++) acc[c][p] = fmaf(v[kw + p], wv, acc[c][p]);
                    }
            }
        }
    }

#pragma unroll
    for (int c = 0; c < 3; c++) {
        float bv = bias[c];
        size_t base = (((size_t)b * 3 + c) * 61 + z) * 61 * 61 + (size_t)y * 61;
#pragma unroll
        for (int p = 0; p < 8; p++) {
            int x = x0 + p;
            if (x < 61) out[base + x] = tanhf(acc[c][p] + bv);
        }
    }
}

// ---------------------------------------------------------------------------

extern "C" void kernel_launch(void* const* d_in, const int* in_sizes, int n_in,
                              void* d_out, int out_size)
{
    const float* x   = (const float*)d_in[0];
    const float* ew1 = (const float*)d_in[1];  const float* eb1 = (const float*)d_in[2];
    const float* ew2 = (const float*)d_in[3];  const float* eb2 = (const float*)d_in[4];
    const float* ew3 = (const float*)d_in[5];  const float* eb3 = (const float*)d_in[6];
    const float* ew4 = (const float*)d_in[7];  const float* eb4 = (const float*)d_in[8];
    const float* cb  = (const float*)d_in[9];
    const float* dw1 = (const float*)d_in[10]; const float* db1 = (const float*)d_in[11];
    const float* dw2 = (const float*)d_in[12]; const float* db2 = (const float*)d_in[13];
    const float* dw3 = (const float*)d_in[14]; const float* db3 = (const float*)d_in[15];
    const float* dw4 = (const float*)d_in[16]; const float* db4 = (const float*)d_in[17];

    float* out = (float*)d_out;
    const int RECON = 2 * 3 * 61 * 61 * 61;
    float* idx_out = (out_size >= RECON + 1024) ? (out + RECON) : nullptr;

    float *h1, *h2, *h3, *lat, *d3;
    unsigned *q2, *d1h, *d2h, *wpk1, *wpk2, *wpk3;
    cudaGetSymbolAddress((void**)&h1, g_h1);
    cudaGetSymbolAddress((void**)&h2, g_h2);
    cudaGetSymbolAddress((void**)&h3, g_h3);
    cudaGetSymbolAddress((void**)&lat, g_lat);
    cudaGetSymbolAddress((void**)&d3, g_d3);
    cudaGetSymbolAddress((void**)&q2, g_q2);
    cudaGetSymbolAddress((void**)&d1h, g_d1h);
    cudaGetSymbolAddress((void**)&d2h, g_d2h);
    cudaGetSymbolAddress((void**)&wpk1, g_wpk1);
    cudaGetSymbolAddress((void**)&wpk2, g_wpk2);
    cudaGetSymbolAddress((void**)&wpk3, g_wpk3);

    // weight repacks
    repackW<256, 256><<<(8 * 4 * 64 * 1536 + 255) / 256, 256>>>(dw1, wpk1);
    repackW<256, 128><<<(8 * 2 * 64 * 1536 + 255) / 256, 256>>>(dw2, wpk2);
    repackW<128, 64><<<(8 * 1 * 32 * 1536 + 255) / 256, 256>>>(dw3, wpk3);

    // encoder (scalar fp32 per-tap loads; exact argmin)
    conv_s2_relu<3, 64, 32, 8, 4><<<dim3(64, 8, 2), 128>>>(x, ew1, eb1, h1);
    conv_s2_relu<64, 128, 16, 8, 4><<<dim3(8, 16, 2), 128>>>(h1, ew2, eb2, h2);
    conv_s2_relu<128, 256, 8, 2, 2><<<dim3(2, 128, 2), 128>>>(h2, ew3, eb3, h3);
    conv1x1<<<dim3(4, 32, 2), 128>>>(h3, ew4, eb4, lat);

    // vector quantization (writes packed q + idx)
    vq_kernel<<<128, 128>>>(lat, cb, q2, idx_out);

    // decoder: packed-h2 activation chain
    convT_mma<256, 256, 8, 2, 8, true><<<dim3(4, 4, 16), 256>>>(q2, wpk1, db1, nullptr, d1h);
    convT_mma<256, 128, 16, 1, 8, true><<<dim3(32, 2, 16), 256>>>(d1h, wpk2, db2, nullptr, d2h);
    convT_mma<128, 64, 32, 1, 4, false><<<dim3(256, 1, 16), 256>>>(d2h, wpk3, db3, d3, nullptr);
    conv_final_tanh<<<dim3(4, 61, 2), 128>>>(d3, dw4, db4, out);
}